// round 16
// baseline (speedup 1.0000x reference)
#include <cuda_runtime.h>
#include <cstdint>

#define T_LEN   1024
#define NB      256
#define C_CLASS 128
#define S_TGT   128
#define NCF     (NB * C_CLASS)
#define ROWB    (NCF * 4)
#define NEGV    -1e30f
#define FULLM   0xffffffffu
#define SLACK   12.0f
#define NH      5
#define HALF    (8 * C_CLASS)

__device__ float        g_partial[NB];
__device__ unsigned int g_count;

#define CP16(d,s)  asm volatile("cp.async.ca.shared.global [%0], [%1], 16;" :: "r"(d), "l"(s))
#define CPCOMMIT() asm volatile("cp.async.commit_group;")
#define CPWAIT(N)  asm volatile("cp.async.wait_group %0;" :: "n"(N))
#define BARW(id)   asm volatile("bar.sync %0, 64;" :: "r"(id) : "memory")

// ===== forward pair: alpha over t=1..steps. LO (leader) states 0..127,
// HI (lagger) states 128..256; 4 states/lane; R9-validated lag protocol. =====
template<bool LAG>
__device__ __forceinline__ void run_fwd_pair(
    const float* lpn, const int* tg, int steps,
    float* ring, unsigned ring_s, const char* srcb,
    float (*bnd)[8], float* lsp, float* sa, int lane, int barid)
{
    const int base = LAG ? 64 : 0;
    int2 ev = *(const int2*)(tg + base + 2 * lane);
    const int e0 = ev.x, e1 = ev.y;
    const int prevl = (LAG || lane > 0) ? tg[base + 2 * lane - 1] : 0;
    const float sk0 = (!LAG && lane == 0) ? 0.f : ((e0 != prevl) ? 1.f : 0.f);
    const float sk1 = (e1 != e0) ? 1.f : 0.f;

    float a0=0.f, a1=0.f, a2=0.f, a3=0.f, a4=0.f;
    if (!LAG && lane == 0) { a0 = __expf(lpn[0]); a1 = __expf(lpn[e0]); }
    float ls = 0.f, lsB = 0.f, f = (!LAG && lane == 0) ? 0.f : 1.f;

    const int K = steps >> 3, R = steps & 7;
    float lb = 0.f, r0 = 0.f, r1 = 0.f;

    auto renorm = [&](float clampls) {
        float m = fmaxf(fmaxf(a0, a1), fmaxf(a2, a3));
        if (LAG) m = fmaxf(m, a4);
        float lsc = (m > 0.f) ? (ls + __logf(m)) : -1e37f;
        if (LAG && lane == 0) lsc = fmaxf(lsc, clampls - SLACK);
        float x;
        x=__shfl_up_sync(FULLM,lsc,1);  if(lane>=1)  lsc=fmaxf(lsc,x-SLACK);
        x=__shfl_up_sync(FULLM,lsc,2);  if(lane>=2)  lsc=fmaxf(lsc,x-2.f*SLACK);
        x=__shfl_up_sync(FULLM,lsc,4);  if(lane>=4)  lsc=fmaxf(lsc,x-4.f*SLACK);
        x=__shfl_up_sync(FULLM,lsc,8);  if(lane>=8)  lsc=fmaxf(lsc,x-8.f*SLACK);
        x=__shfl_up_sync(FULLM,lsc,16); if(lane>=16) lsc=fmaxf(lsc,x-16.f*SLACK);
        float sc = (m > 0.f) ? __expf(0.5f * (ls - lsc)) : 0.f;
        a0=(a0*sc)*sc; a1=(a1*sc)*sc; a2=(a2*sc)*sc; a3=(a3*sc)*sc;
        if (LAG) a4=(a4*sc)*sc;
        ls = lsc;
        float lp = __shfl_up_sync(FULLM, ls, 1);
        f = __expf(lp - ls);
        if (!LAG && lane == 0) f = 0.f;
    };

    auto block8 = [&](int j, int hj) {
        const float* ph = ring + hj * HALF;
        int hn = hj + 1; if (hn == NH) hn = 0;
        const float* pn = ring + hn * HALF;
        float fw = 0.f;
        const float* bb = bnd[j & 3];
        float*       bw = bnd[j & 3];
        if (LAG) fw = __expf(lsp[j & 3] - ls);
        #pragma unroll
        for (int u = 0; u < 8; ++u) {
            float lbn, w0, w1;
            if (u < 7) { const int o = (u + 1) * C_CLASS;
                         lbn = ph[o]; w0 = ph[o + e0]; w1 = ph[o + e1]; }
            else       { lbn = pn[0]; w0 = pn[e0]; w1 = pn[e1]; }
            float s0 = __expf(w0 - lbn), s1 = __expf(w1 - lbn);
            if (!LAG) { if (lane == 31) bw[u] = a3; }   // boundary state 127
            float shv = __shfl_up_sync(FULLM, a3, 1);
            float nbv = shv * f;
            if (LAG) { float cc = bb[u]; if (lane == 0) nbv = cc * fw; }
            lsB += lb;
            float n0 = a0 + nbv;
            float n1 = r0 * fmaf(sk0, nbv, a0 + a1);
            float n2 = a2 + a1;
            float n3 = r1 * fmaf(sk1, a1, a2 + a3);
            float n4 = a4 + a3;
            a0=n0; a1=n1; a2=n2; a3=n3; if (LAG) a4=n4;
            lb = lbn; r0 = s0; r1 = s1;
        }
    };

    auto prefetch = [&](int blk, int h) {
        unsigned d = ring_s + (unsigned)(h * (HALF * 4)) + lane * 16;
        int rs = 1 + 8 * blk;
        #pragma unroll
        for (int q = 0; q < 8; ++q) {
            int rr = rs + q; if (rr > T_LEN - 1) rr = T_LEN - 1;
            CP16(d + q * 512, srcb + (size_t)rr * ROWB);
        }
        CPCOMMIT();
    };

    if (!LAG) {
        if (lane == 0) lsp[0] = 0.f;
        #pragma unroll
        for (int k = 0; k < 3; ++k) prefetch(k, k);
        CPWAIT(2);
        lb = ring[0]; r0 = __expf(ring[e0] - lb); r1 = __expf(ring[e1] - lb);
    }

    int hk = 0, hpf = 3, hj = 0;
    for (int k = 0; k < K; ++k) {
        if (!LAG) {
            CPWAIT(1);
            block8(k, hk);
            prefetch(k + 3, hpf);
            renorm(0.f);
            if (lane == 31) lsp[(k + 1) & 3] = ls;
            if (++hk == NH) hk = 0;
            if (++hpf == NH) hpf = 0;
        } else if (k >= 1) {
            if (k == 1) { lb = ring[0]; r0 = __expf(ring[e0] - lb); r1 = __expf(ring[e1] - lb); }
            block8(k - 1, hj);
            renorm(lsp[k & 3]);
            if (++hj == NH) hj = 0;
        }
        BARW(barid);
    }
    // tail1: leader remainder (publishes bnd[K&3]); lagger block K-1
    if (!LAG) {
        float* bw = bnd[K & 3];
        const float* ph = ring + hk * HALF;
        for (int i = 0; i < R; ++i) {
            const int o = (i + 1) * C_CLASS;
            float lbn = ph[o], w0 = ph[o + e0], w1 = ph[o + e1];
            float s0 = __expf(w0 - lbn), s1 = __expf(w1 - lbn);
            if (lane == 31) bw[i] = a3;
            float shv = __shfl_up_sync(FULLM, a3, 1);
            float nbv = shv * f;
            lsB += lb;
            float n0 = a0 + nbv;
            float n1 = r0 * fmaf(sk0, nbv, a0 + a1);
            float n2 = a2 + a1;
            float n3 = r1 * fmaf(sk1, a1, a2 + a3);
            a0=n0; a1=n1; a2=n2; a3=n3;
            lb = lbn; r0 = s0; r1 = s1;
        }
    } else if (K >= 1) {
        if (K == 1) { lb = ring[0]; r0 = __expf(ring[e0] - lb); r1 = __expf(ring[e1] - lb); }
        block8(K - 1, hj);
        renorm(lsp[K & 3]);
        if (++hj == NH) hj = 0;
    }
    BARW(barid);
    // tail2: lagger remainder
    if (LAG) {
        const float* bb = bnd[K & 3];
        float fw = __expf(lsp[K & 3] - ls);
        const float* ph = ring + hj * HALF;
        for (int i = 0; i < R; ++i) {
            const int o = (i + 1) * C_CLASS;
            float lbn = ph[o], w0 = ph[o + e0], w1 = ph[o + e1];
            float s0 = __expf(w0 - lbn), s1 = __expf(w1 - lbn);
            float shv = __shfl_up_sync(FULLM, a3, 1);
            float nbv = (lane == 0) ? bb[i] * fw : shv * f;
            lsB += lb;
            float n0 = a0 + nbv;
            float n1 = r0 * fmaf(sk0, nbv, a0 + a1);
            float n2 = a2 + a1;
            float n3 = r1 * fmaf(sk1, a1, a2 + a3);
            float n4 = a4 + a3;
            a0=n0; a1=n1; a2=n2; a3=n3; a4=n4;
            lb = lbn; r0 = s0; r1 = s1;
        }
    }
    BARW(barid);
    if (!LAG) CPWAIT(0);
    BARW(barid);                       // all in-flight copies landed pre-overlay

    const float lt = ls + lsB;
    const int sbase = base * 2 + 4 * lane;
    sa[sbase+0] = (a0 > 0.f) ? __logf(a0) + lt : NEGV;
    sa[sbase+1] = (a1 > 0.f) ? __logf(a1) + lt : NEGV;
    sa[sbase+2] = (a2 > 0.f) ? __logf(a2) + lt : NEGV;
    sa[sbase+3] = (a3 > 0.f) ? __logf(a3) + lt : NEGV;
    if (LAG && lane == 31) sa[256] = (a4 > 0.f) ? __logf(a4) + lt : NEGV;
}

// ===== backward pair: beta over rows inLen-2 .. tm+1. HI (leader) states
// 128..256, LO (lagger) states 0..127; mirror of the forward protocol. =====
template<bool LAG>
__device__ __forceinline__ void run_bwd_pair(
    const float* lpn, const int* tg, int steps, int inLen, int TL,
    float* ring, unsigned ring_s, const char* srcb,
    float (*bnd)[8][2], float* lsp, float* sb, int lane, int barid)
{
    const int base = LAG ? 0 : 64;
    int2 ev = *(const int2*)(tg + base + 2 * lane);
    const int e0 = ev.x, e1 = ev.y;
    const int eN = (lane < 31 || LAG) ? tg[base + 2 * lane + 2] : 0;
    const float K1 = (e1 != e0) ? 1.f : 0.f;
    const float K2 = ((lane < 31 || LAG) && eN != e1) ? 1.f : 0.f;

    float b0=0.f, b1=0.f, b2=0.f, b3=0.f, b4=0.f;
    float ls = 0.f, f = 1.f;
    const float* rl = lpn + (size_t)(inLen - 1) * NCF;
    const float lbl = __ldg(rl);
    float lsB = lbl;
    {
        const int fin = 2 * TL;
        const int s0g = base * 2 + 4 * lane;
        int d = fin - s0g;
        if (d >= 0 && d < 4) { if (d == 0) b0 = 1.f; else if (d == 2) b2 = 1.f; }
        int d1 = fin - 1 - s0g;
        if (d1 >= 0 && d1 < 4) {
            float rr = __expf(__ldg(rl + tg[TL - 1]) - lbl);
            if (d1 == 1) b1 = rr; else if (d1 == 3) b3 = rr;
        }
        if (!LAG && lane == 31 && fin == 256) b4 = 1.f;
    }

    const int K = steps >> 3, R = steps & 7;
    float lb = 0.f, r0 = 0.f, r1 = 0.f;

    auto renorm = [&](float clampls) {
        float m = fmaxf(fmaxf(b0, b1), fmaxf(b2, b3));
        if (!LAG) m = fmaxf(m, b4);
        float lsc = (m > 0.f) ? (ls + __logf(m)) : -1e37f;
        if (LAG && lane == 31) lsc = fmaxf(lsc, clampls - SLACK);
        float x;
        x=__shfl_down_sync(FULLM,lsc,1);  if(lane<=30) lsc=fmaxf(lsc,x-SLACK);
        x=__shfl_down_sync(FULLM,lsc,2);  if(lane<=29) lsc=fmaxf(lsc,x-2.f*SLACK);
        x=__shfl_down_sync(FULLM,lsc,4);  if(lane<=27) lsc=fmaxf(lsc,x-4.f*SLACK);
        x=__shfl_down_sync(FULLM,lsc,8);  if(lane<=23) lsc=fmaxf(lsc,x-8.f*SLACK);
        x=__shfl_down_sync(FULLM,lsc,16); if(lane<=15) lsc=fmaxf(lsc,x-16.f*SLACK);
        float sc = (m > 0.f) ? __expf(0.5f * (ls - lsc)) : 0.f;
        b0=(b0*sc)*sc; b1=(b1*sc)*sc; b2=(b2*sc)*sc; b3=(b3*sc)*sc;
        if (!LAG) b4=(b4*sc)*sc;
        ls = lsc;
        float lp = __shfl_down_sync(FULLM, ls, 1);
        f = __expf(lp - ls);
    };

    auto block8 = [&](int j, int hj) {
        const float* ph = ring + hj * HALF;
        int hn = hj + 1; if (hn == NH) hn = 0;
        const float* pn = ring + hn * HALF;
        float fw = 0.f;
        const float (*bbr)[2] = bnd[j & 3];
        float       (*bwr)[2] = bnd[j & 3];
        if (LAG) fw = __expf(lsp[j & 3] - ls);
        #pragma unroll
        for (int u = 0; u < 8; ++u) {
            float lbn, w0, w1;
            if (u < 7) { const int o = (u + 1) * C_CLASS;
                         lbn = ph[o]; w0 = ph[o + e0]; w1 = ph[o + e1]; }
            else       { lbn = pn[0]; w0 = pn[e0]; w1 = pn[e1]; }
            float s0 = __expf(w0 - lbn), s1 = __expf(w1 - lbn);
            if (!LAG) { if (lane == 0) { bwr[u][0] = b0; bwr[u][1] = b1; } }
            float c0 = __shfl_down_sync(FULLM, b0, 1);
            float c1 = __shfl_down_sync(FULLM, b1, 1);
            if (LAG) {
                float p0 = bbr[u][0], p1 = bbr[u][1];
                if (lane == 31) { c0 = p0 * fw; c1 = p1 * fw; }
                else            { c0 *= f; c1 *= f; }
            } else {
                if (lane == 31) { c0 = b4; c1 = 0.f; }
                else            { c0 *= f; c1 *= f; }
            }
            lsB += lb;
            float n0 = b0 + b1;
            float n1 = r0 * fmaf(K1, b3, b1 + b2);
            float n2 = b2 + b3;
            float n3 = r1 * fmaf(K2, c1, b3 + c0);
            b0=n0; b1=n1; b2=n2; b3=n3;          // b4 (state 256) unchanged
            lb = lbn; r0 = s0; r1 = s1;
        }
    };

    auto prefetch = [&](int blk, int h) {
        unsigned d = ring_s + (unsigned)(h * (HALF * 4)) + lane * 16;
        #pragma unroll
        for (int q = 0; q < 8; ++q) {
            int row = inLen - 2 - (8 * blk + q); if (row < 0) row = 0;
            CP16(d + q * 512, srcb + (size_t)row * ROWB);
        }
        CPCOMMIT();
    };

    if (!LAG) {
        if (lane == 0) lsp[0] = 0.f;
        #pragma unroll
        for (int k = 0; k < 3; ++k) prefetch(k, k);
        CPWAIT(2);
        lb = ring[0]; r0 = __expf(ring[e0] - lb); r1 = __expf(ring[e1] - lb);
    }

    int hk = 0, hpf = 3, hj = 0;
    for (int k = 0; k < K; ++k) {
        if (!LAG) {
            CPWAIT(1);
            block8(k, hk);
            prefetch(k + 3, hpf);
            renorm(0.f);
            if (lane == 0) lsp[(k + 1) & 3] = ls;
            if (++hk == NH) hk = 0;
            if (++hpf == NH) hpf = 0;
        } else if (k >= 1) {
            if (k == 1) { lb = ring[0]; r0 = __expf(ring[e0] - lb); r1 = __expf(ring[e1] - lb); }
            block8(k - 1, hj);
            renorm(lsp[k & 3]);
            if (++hj == NH) hj = 0;
        }
        BARW(barid);
    }
    // tail1: leader remainder (publishes bnd[K&3]); lagger block K-1
    if (!LAG) {
        float (*bwr)[2] = bnd[K & 3];
        const float* ph = ring + hk * HALF;
        for (int i = 0; i < R; ++i) {
            const int o = (i + 1) * C_CLASS;
            float lbn = ph[o], w0 = ph[o + e0], w1 = ph[o + e1];
            float s0 = __expf(w0 - lbn), s1 = __expf(w1 - lbn);
            if (lane == 0) { bwr[i][0] = b0; bwr[i][1] = b1; }
            float c0 = __shfl_down_sync(FULLM, b0, 1);
            float c1 = __shfl_down_sync(FULLM, b1, 1);
            if (lane == 31) { c0 = b4; c1 = 0.f; } else { c0 *= f; c1 *= f; }
            lsB += lb;
            float n0 = b0 + b1;
            float n1 = r0 * fmaf(K1, b3, b1 + b2);
            float n2 = b2 + b3;
            float n3 = r1 * fmaf(K2, c1, b3 + c0);
            b0=n0; b1=n1; b2=n2; b3=n3;
            lb = lbn; r0 = s0; r1 = s1;
        }
    } else if (K >= 1) {
        if (K == 1) { lb = ring[0]; r0 = __expf(ring[e0] - lb); r1 = __expf(ring[e1] - lb); }
        block8(K - 1, hj);
        renorm(lsp[K & 3]);
        if (++hj == NH) hj = 0;
    }
    BARW(barid);
    // tail2: lagger remainder
    if (LAG) {
        const float (*bbr)[2] = bnd[K & 3];
        float fw = __expf(lsp[K & 3] - ls);
        const float* ph = ring + hj * HALF;
        for (int i = 0; i < R; ++i) {
            const int o = (i + 1) * C_CLASS;
            float lbn = ph[o], w0 = ph[o + e0], w1 = ph[o + e1];
            float s0 = __expf(w0 - lbn), s1 = __expf(w1 - lbn);
            float c0 = __shfl_down_sync(FULLM, b0, 1);
            float c1 = __shfl_down_sync(FULLM, b1, 1);
            if (lane == 31) { c0 = bbr[i][0] * fw; c1 = bbr[i][1] * fw; }
            else            { c0 *= f; c1 *= f; }
            lsB += lb;
            float n0 = b0 + b1;
            float n1 = r0 * fmaf(K1, b3, b1 + b2);
            float n2 = b2 + b3;
            float n3 = r1 * fmaf(K2, c1, b3 + c0);
            b0=n0; b1=n1; b2=n2; b3=n3;
            lb = lbn; r0 = s0; r1 = s1;
        }
    }
    BARW(barid);
    if (!LAG) CPWAIT(0);
    BARW(barid);

    const float lt = ls + lsB;
    const int sbase = base * 2 + 4 * lane;
    sb[sbase+0] = (b0 > 0.f) ? __logf(b0) + lt : NEGV;
    sb[sbase+1] = (b1 > 0.f) ? __logf(b1) + lt : NEGV;
    sb[sbase+2] = (b2 > 0.f) ? __logf(b2) + lt : NEGV;
    sb[sbase+3] = (b3 > 0.f) ? __logf(b3) + lt : NEGV;
    if (!LAG && lane == 31) sb[256] = (b4 > 0.f) ? __logf(b4) + lt : NEGV;
    if (!LAG && lane == 0)  sb[257] = NEGV;
}

__global__ void __launch_bounds__(128, 2) ctc_kernel(
    const float* __restrict__ log_probs,
    const int*   __restrict__ targets,
    const int*   __restrict__ input_lengths,
    const int*   __restrict__ target_lengths,
    float*       __restrict__ out)
{
    __shared__ float ring_f[NH * HALF];   // 20KB, fwd pair; overlaid with sa
    __shared__ float ring_b[NH * HALF];   // 20KB, bwd pair; overlaid with sb
    __shared__ float bndf[4][8];
    __shared__ float bndb[4][8][2];
    __shared__ float lsf[4];
    __shared__ float lsq[4];

    const int wid  = threadIdx.x >> 5;
    const int lane = threadIdx.x & 31;
    const int n    = blockIdx.x;

    const float* lpn = log_probs + (size_t)n * C_CLASS;
    const int*   tg  = targets + n * S_TGT;
    const int inLen  = input_lengths[n];
    const int TL     = target_lengths[n];
    const int tm     = (inLen - 1) >> 1;
    const char* srcb = (const char*)lpn + lane * 16;

    const unsigned rf_s = (unsigned)__cvta_generic_to_shared(ring_f);
    const unsigned rb_s = (unsigned)__cvta_generic_to_shared(ring_b);

    if      (wid == 0) run_fwd_pair<false>(lpn, tg, tm, ring_f, rf_s, srcb, bndf, lsf, ring_f, lane, 1);
    else if (wid == 1) run_fwd_pair<true >(lpn, tg, tm, ring_f, rf_s, srcb, bndf, lsf, ring_f, lane, 1);
    else if (wid == 2) run_bwd_pair<false>(lpn, tg, inLen - 2 - tm, inLen, TL, ring_b, rb_s, srcb, bndb, lsq, ring_b, lane, 2);
    else               run_bwd_pair<true >(lpn, tg, inLen - 2 - tm, inLen, TL, ring_b, rb_s, srcb, bndb, lsq, ring_b, lane, 2);
    __syncthreads();

    if (wid == 0) {
        // ---- combine: P = sum_l alpha_tm(l)*(b(l)+b(l+1)+skip(l+2)*b(l+2)) ----
        const float* sa = ring_f;
        const float* sb = ring_b;
        int4 tv = *(const int4*)(tg + 4 * lane);
        const int e0 = tv.x, e1 = tv.y, e2 = tv.z, e3 = tv.w;
        const float g1 = (e1 != e0) ? 1.f : 0.f;
        const float g2 = (e2 != e1) ? 1.f : 0.f;
        const float g3 = (e3 != e2) ? 1.f : 0.f;
        const float g4 = (lane < 31 && tg[4 * lane + 4] != e3) ? 1.f : 0.f;
        float E[8];
        const int l0 = 8 * lane;
        #pragma unroll
        for (int j = 0; j < 8; ++j) {
            float fl = (j==1)?g1 : (j==3)?g2 : (j==5)?g3 : (j==7)?g4 : 0.f;
            float x0 = sb[l0 + j];
            float x1 = sb[l0 + j + 1];
            float x2 = (fl > 0.f) ? sb[l0 + j + 2] : NEGV;
            float m3 = fmaxf(x0, fmaxf(x1, x2));
            float lse = m3 + __logf(__expf(x0-m3) + __expf(x1-m3) + __expf(x2-m3));
            E[j] = sa[l0 + j] + lse;
        }
        float E8 = (lane == 31) ? (sa[256] + sb[256]) : NEGV;
        float mx = E8;
        #pragma unroll
        for (int j = 0; j < 8; ++j) mx = fmaxf(mx, E[j]);
        #pragma unroll
        for (int o = 16; o > 0; o >>= 1)
            mx = fmaxf(mx, __shfl_xor_sync(FULLM, mx, o));
        float s = __expf(E8 - mx);
        #pragma unroll
        for (int j = 0; j < 8; ++j) s += __expf(E[j] - mx);
        #pragma unroll
        for (int o = 16; o > 0; o >>= 1)
            s += __shfl_xor_sync(FULLM, s, o);
        if (lane == 0) {
            float loss = -(mx + __logf(s));
            g_partial[n] = loss / (float)TL;
            __threadfence();
        }
        __syncwarp();
        unsigned tk = 0;
        if (lane == 0) tk = atomicAdd(&g_count, 1u);
        tk = __shfl_sync(FULLM, tk, 0);
        if (tk == NB - 1) {
            __threadfence();
            float acc = 0.f;
            #pragma unroll
            for (int i = 0; i < NB / 32; ++i)
                acc += __ldcg(&g_partial[lane + 32 * i]);
            #pragma unroll
            for (int o = 16; o > 0; o >>= 1)
                acc += __shfl_down_sync(FULLM, acc, o);
            if (lane == 0) {
                out[0] = acc * (1.f / (float)NB);
                g_count = 0;
            }
        }
    }
}

extern "C" void kernel_launch(void* const* d_in, const int* in_sizes, int n_in,
                              void* d_out, int out_size)
{
    const float* log_probs      = (const float*)d_in[0];
    const int*   targets        = (const int*)  d_in[1];
    const int*   input_lengths  = (const int*)  d_in[2];
    const int*   target_lengths = (const int*)  d_in[3];

    ctc_kernel<<<NB, 128>>>(log_probs, targets, input_lengths,
                            target_lengths, (float*)d_out);
}

// round 17
// speedup vs baseline: 1.0391x; 1.0391x over previous
#include <cuda_runtime.h>
#include <cstdint>

#define T_LEN   1024
#define NB      256
#define C_CLASS 128
#define S_TGT   128
#define NCF     (NB * C_CLASS)
#define ROWB    (NCF * 4)
#define NEGV    -1e30f
#define FULLM   0xffffffffu
#define SLACK   12.0f
#define HALF    (8 * C_CLASS)      // floats per ring half (8 rows)

__device__ float        g_partial[NB];
__device__ unsigned int g_count;

#define CP16(d,s)  asm volatile("cp.async.ca.shared.global [%0], [%1], 16;" :: "r"(d), "l"(s))
#define CPCOMMIT() asm volatile("cp.async.commit_group;")
#define CPWAIT(N)  asm volatile("cp.async.wait_group %0;" :: "n"(N))

// ---------------- forward: alpha over t = 1..tm ----------
__device__ __forceinline__ void run_fwd(
    const float* lpn, const int* tg, int tm,
    float* ring, unsigned ring_s, const char* srcb, float* sa, int lane)
{
    int4 tv = *(const int4*)(tg + 4 * lane);
    const int e0 = tv.x, e1 = tv.y, e2 = tv.z, e3 = tv.w;
    const int prev = (lane == 0) ? -1 : tg[4 * lane - 1];
    const float sk0 = (lane > 0 && e0 != prev) ? 1.f : 0.f;
    const float sk1 = (e1 != e0) ? 1.f : 0.f;
    const float sk2 = (e2 != e1) ? 1.f : 0.f;
    const float sk3 = (e3 != e2) ? 1.f : 0.f;

    float a0=0.f,a1=0.f,a2=0.f,a3=0.f,a4=0.f,a5=0.f,a6=0.f,a7=0.f,a8=0.f;
    if (lane == 0) { a0 = __expf(lpn[0]); a1 = __expf(lpn[e0]); }
    float ls = 0.f, lsB = 0.f, f = (lane == 0) ? 0.f : 1.f;

#define FSTEP(lbn,w0,w1,w2,w3) do {                                            \
    float s0=__expf((w0)-(lbn)), s1=__expf((w1)-(lbn));                        \
    float s2=__expf((w2)-(lbn)), s3=__expf((w3)-(lbn));                        \
    lsB += lb;                                                                 \
    float nb = __shfl_up_sync(FULLM, a7, 1) * f;                               \
    float n0 = a0 + nb;                                                        \
    float n1 = r0 * fmaf(sk0, nb, a0 + a1);                                    \
    float n2 = a2 + a1;                                                        \
    float n3 = r1 * fmaf(sk1, a1, a2 + a3);                                    \
    float n4 = a4 + a3;                                                        \
    float n5 = r2 * fmaf(sk2, a3, a4 + a5);                                    \
    float n6 = a6 + a5;                                                        \
    float n7 = r3 * fmaf(sk3, a5, a6 + a7);                                    \
    float n8 = a8 + a7;                                                        \
    a0=n0;a1=n1;a2=n2;a3=n3;a4=n4;a5=n5;a6=n6;a7=n7;a8=n8;                     \
    lb=(lbn); r0=s0; r1=s1; r2=s2; r3=s3;                                      \
} while (0)

    #pragma unroll
    for (int k = 0; k < 3; ++k) {                 // rows 1..24
        unsigned d = ring_s + (unsigned)(k * (HALF * 4)) + lane * 16;
        const char* s = srcb + (size_t)(1 + 8 * k) * ROWB;
        #pragma unroll
        for (int j = 0; j < 8; ++j) CP16(d + j * 512, s + (size_t)j * ROWB);
        CPCOMMIT();
    }
    CPWAIT(1);
    float lb = ring[0];
    float r0 = __expf(ring[e0] - lb), r1 = __expf(ring[e1] - lb);
    float r2 = __expf(ring[e2] - lb), r3 = __expf(ring[e3] - lb);

    const int end = tm + 1;                       // steps tt = 1..tm
    int t = 1, h = 0;
    while (t + 8 <= end) {
        const int nh = (h == 2) ? 0 : h + 1;
        const float* ph = ring + h * HALF;
        const float* pn = ring + nh * HALF;
        #pragma unroll
        for (int u = 0; u < 8; ++u) {
            float lbn, w0, w1, w2, w3;
            if (u < 7) { int o = (u + 1) * C_CLASS;
                lbn = ph[o]; w0 = ph[o+e0]; w1 = ph[o+e1]; w2 = ph[o+e2]; w3 = ph[o+e3]; }
            else { lbn = pn[0]; w0 = pn[e0]; w1 = pn[e1]; w2 = pn[e2]; w3 = pn[e3]; }
            FSTEP(lbn, w0, w1, w2, w3);
        }
        {   // prefetch rows t+24..t+31 into half h (clamp hoisted per block)
            unsigned d = ring_s + (unsigned)(h * (HALF * 4)) + lane * 16;
            int rs = t + 24;
            if (rs + 7 <= T_LEN - 1) {
                const char* s = srcb + (size_t)rs * ROWB;
                #pragma unroll
                for (int j = 0; j < 8; ++j) CP16(d + j * 512, s + (size_t)j * ROWB);
            } else {
                #pragma unroll
                for (int j = 0; j < 8; ++j) {
                    int rr = rs + j; if (rr > T_LEN - 1) rr = T_LEN - 1;
                    CP16(d + j * 512, srcb + (size_t)rr * ROWB);
                }
            }
            CPCOMMIT();
        }
        {   // per-lane renorm + upward bounded-slack scan (single-mul rescale)
            float m = fmaxf(fmaxf(fmaxf(a0,a1),fmaxf(a2,a3)),
                            fmaxf(fmaxf(a4,a5),fmaxf(a6,a7)));
            m = fmaxf(m, a8);
            float lsc = (m > 0.f) ? (ls + __logf(m)) : -1e37f;
            float x;
            x=__shfl_up_sync(FULLM,lsc,1);  if(lane>=1)  lsc=fmaxf(lsc,x-SLACK);
            x=__shfl_up_sync(FULLM,lsc,2);  if(lane>=2)  lsc=fmaxf(lsc,x-2.f*SLACK);
            x=__shfl_up_sync(FULLM,lsc,4);  if(lane>=4)  lsc=fmaxf(lsc,x-4.f*SLACK);
            x=__shfl_up_sync(FULLM,lsc,8);  if(lane>=8)  lsc=fmaxf(lsc,x-8.f*SLACK);
            x=__shfl_up_sync(FULLM,lsc,16); if(lane>=16) lsc=fmaxf(lsc,x-16.f*SLACK);
            float sc = (m > 0.f) ? __expf(ls - lsc) : 0.f;
            a0*=sc; a1*=sc; a2*=sc; a3*=sc; a4*=sc;
            a5*=sc; a6*=sc; a7*=sc; a8*=sc;
            ls = lsc;
            float lp = __shfl_up_sync(FULLM, ls, 1);
            f = (lane == 0) ? 0.f : __expf(lp - ls);
        }
        t += 8; h = nh;
        CPWAIT(1);
    }
    for (int tt = t; tt < end; ++tt) {            // remainder (<8 steps)
        int r = tt + 1; if (r > T_LEN - 1) r = T_LEN - 1;
        int b = (r - 1) >> 3;
        const float* q = ring + (b % 3) * HALF + ((r - 1) & 7) * C_CLASS;
        FSTEP(q[0], q[e0], q[e1], q[e2], q[e3]);
    }
    CPWAIT(0);
    __syncwarp();                                 // ring reads done before overlay
    const float lt = ls + lsB;
    sa[8*lane+0]=(a0>0.f)?__logf(a0)+lt:NEGV;
    sa[8*lane+1]=(a1>0.f)?__logf(a1)+lt:NEGV;
    sa[8*lane+2]=(a2>0.f)?__logf(a2)+lt:NEGV;
    sa[8*lane+3]=(a3>0.f)?__logf(a3)+lt:NEGV;
    sa[8*lane+4]=(a4>0.f)?__logf(a4)+lt:NEGV;
    sa[8*lane+5]=(a5>0.f)?__logf(a5)+lt:NEGV;
    sa[8*lane+6]=(a6>0.f)?__logf(a6)+lt:NEGV;
    sa[8*lane+7]=(a7>0.f)?__logf(a7)+lt:NEGV;
    if (lane == 31) sa[256]=(a8>0.f)?__logf(a8)+lt:NEGV;
#undef FSTEP
}

// ---------------- backward: beta over t = inLen-1 .. tm+1 -------------------
__device__ __forceinline__ void run_bwd(
    const float* lpn, const int* tg, int tm, int inLen, int TL,
    float* ring, unsigned ring_s, const char* srcb, float* sb, int lane)
{
    int4 tv = *(const int4*)(tg + 4 * lane);
    const int e0 = tv.x, e1 = tv.y, e2 = tv.z, e3 = tv.w;
    const int eN = (lane < 31) ? tg[4 * lane + 4] : 0;
    const float K1 = (e1 != e0) ? 1.f : 0.f;
    const float K2 = (e2 != e1) ? 1.f : 0.f;
    const float K3 = (e3 != e2) ? 1.f : 0.f;
    const float K4 = (lane < 31 && eN != e3) ? 1.f : 0.f;

    float b0=0.f,b1=0.f,b2=0.f,b3=0.f,b4=0.f,b5=0.f,b6=0.f,b7=0.f,b8=0.f;
    float ls = 0.f, f = 1.f;
    const float* rl = lpn + (size_t)(inLen - 1) * NCF;
    const float lbl = __ldg(rl);
    float lsB = lbl;
    {
        const int fin = 2 * TL, l0 = 8 * lane;
        int d = fin - l0;
        if (d >= 0 && d < 8) { if (d==0) b0=1.f; else if (d==2) b2=1.f;
                               else if (d==4) b4=1.f; else if (d==6) b6=1.f; }
        int d1 = fin - 1 - l0;
        if (d1 >= 0 && d1 < 8) {
            int ee = (d1==1)?e0:(d1==3)?e1:(d1==5)?e2:e3;
            float rr = __expf(__ldg(rl + ee) - lbl);
            if (d1==1) b1=rr; else if (d1==3) b3=rr;
            else if (d1==5) b5=rr; else b7=rr;
        }
        if (lane == 31 && fin == 256) b8 = 1.f;
    }

#define BSTEP(lbn,w0,w1,w2,w3) do {                                            \
    float s0=__expf((w0)-(lbn)), s1=__expf((w1)-(lbn));                        \
    float s2=__expf((w2)-(lbn)), s3=__expf((w3)-(lbn));                        \
    lsB += lb;                                                                 \
    float c0 = __shfl_down_sync(FULLM, b0, 1);                                 \
    float c1 = __shfl_down_sync(FULLM, b1, 1);                                 \
    if (lane == 31) { c0 = b8; c1 = 0.f; } else { c0 *= f; c1 *= f; }          \
    float n0 = b0 + b1;                                                        \
    float n1 = r0 * fmaf(K1, b3, b1 + b2);                                     \
    float n2 = b2 + b3;                                                        \
    float n3 = r1 * fmaf(K2, b5, b3 + b4);                                     \
    float n4 = b4 + b5;                                                        \
    float n5 = r2 * fmaf(K3, b7, b5 + b6);                                     \
    float n6 = b6 + b7;                                                        \
    float n7 = r3 * fmaf(K4, c1, b7 + c0);                                     \
    float n8 = b8;                                                             \
    b0=n0;b1=n1;b2=n2;b3=n3;b4=n4;b5=n5;b6=n6;b7=n7;b8=n8;                     \
    lb=(lbn); r0=s0; r1=s1; r2=s2; r3=s3;                                      \
} while (0)

    // row(v) = inLen-2-v, stored at half (v>>3)%3, slot v&7
    #pragma unroll
    for (int k = 0; k < 3; ++k) {
        unsigned d = ring_s + (unsigned)(k * (HALF * 4)) + lane * 16;
        #pragma unroll
        for (int j = 0; j < 8; ++j) {
            int row = inLen - 2 - (8 * k + j); if (row < 0) row = 0;
            CP16(d + j * 512, srcb + (size_t)row * ROWB);
        }
        CPCOMMIT();
    }
    CPWAIT(1);
    float lb = ring[0];
    float r0 = __expf(ring[e0] - lb), r1 = __expf(ring[e1] - lb);
    float r2 = __expf(ring[e2] - lb), r3 = __expf(ring[e3] - lb);

    const int S = inLen - 2 - tm;                 // steps v = 0..S-1
    int v = 0, h = 0;
    while (v + 8 <= S) {
        const int nh = (h == 2) ? 0 : h + 1;
        const float* ph = ring + h * HALF;
        const float* pn = ring + nh * HALF;
        #pragma unroll
        for (int u = 0; u < 8; ++u) {
            float lbn, w0, w1, w2, w3;
            if (u < 7) { int o = (u + 1) * C_CLASS;
                lbn = ph[o]; w0 = ph[o+e0]; w1 = ph[o+e1]; w2 = ph[o+e2]; w3 = ph[o+e3]; }
            else { lbn = pn[0]; w0 = pn[e0]; w1 = pn[e1]; w2 = pn[e2]; w3 = pn[e3]; }
            BSTEP(lbn, w0, w1, w2, w3);
        }
        {   // prefetch block v/8+3 into half h (clamp hoisted per block)
            unsigned d = ring_s + (unsigned)(h * (HALF * 4)) + lane * 16;
            int bk = (v >> 3) + 3;
            int rtop = inLen - 2 - 8 * bk;        // first (highest) row of block
            if (rtop - 7 >= 0) {
                const char* s = srcb + (size_t)rtop * ROWB;
                #pragma unroll
                for (int j = 0; j < 8; ++j) CP16(d + j * 512, s - (size_t)j * ROWB);
            } else {
                #pragma unroll
                for (int j = 0; j < 8; ++j) {
                    int row = rtop - j; if (row < 0) row = 0;
                    CP16(d + j * 512, srcb + (size_t)row * ROWB);
                }
            }
            CPCOMMIT();
        }
        {   // per-lane renorm + DOWNWARD bounded-slack scan (single-mul rescale)
            float m = fmaxf(fmaxf(fmaxf(b0,b1),fmaxf(b2,b3)),
                            fmaxf(fmaxf(b4,b5),fmaxf(b6,b7)));
            m = fmaxf(m, b8);
            float lsc = (m > 0.f) ? (ls + __logf(m)) : -1e37f;
            float x;
            x=__shfl_down_sync(FULLM,lsc,1);  if(lane<=30) lsc=fmaxf(lsc,x-SLACK);
            x=__shfl_down_sync(FULLM,lsc,2);  if(lane<=29) lsc=fmaxf(lsc,x-2.f*SLACK);
            x=__shfl_down_sync(FULLM,lsc,4);  if(lane<=27) lsc=fmaxf(lsc,x-4.f*SLACK);
            x=__shfl_down_sync(FULLM,lsc,8);  if(lane<=23) lsc=fmaxf(lsc,x-8.f*SLACK);
            x=__shfl_down_sync(FULLM,lsc,16); if(lane<=15) lsc=fmaxf(lsc,x-16.f*SLACK);
            float sc = (m > 0.f) ? __expf(ls - lsc) : 0.f;
            b0*=sc; b1*=sc; b2*=sc; b3*=sc; b4*=sc;
            b5*=sc; b6*=sc; b7*=sc; b8*=sc;
            ls = lsc;
            float lp = __shfl_down_sync(FULLM, ls, 1);
            f = (lane == 31) ? 0.f : __expf(lp - ls);
        }
        v += 8; h = nh;
        CPWAIT(1);
    }
    for (int vv = v; vv < S; ++vv) {              // remainder (<8 steps)
        int vn = vv + 1;
        const float* q = ring + ((vn >> 3) % 3) * HALF + (vn & 7) * C_CLASS;
        BSTEP(q[0], q[e0], q[e1], q[e2], q[e3]);
    }
    CPWAIT(0);
    __syncwarp();                                 // ring reads done before overlay
    const float lt = ls + lsB;
    sb[8*lane+0]=(b0>0.f)?__logf(b0)+lt:NEGV;
    sb[8*lane+1]=(b1>0.f)?__logf(b1)+lt:NEGV;
    sb[8*lane+2]=(b2>0.f)?__logf(b2)+lt:NEGV;
    sb[8*lane+3]=(b3>0.f)?__logf(b3)+lt:NEGV;
    sb[8*lane+4]=(b4>0.f)?__logf(b4)+lt:NEGV;
    sb[8*lane+5]=(b5>0.f)?__logf(b5)+lt:NEGV;
    sb[8*lane+6]=(b6>0.f)?__logf(b6)+lt:NEGV;
    sb[8*lane+7]=(b7>0.f)?__logf(b7)+lt:NEGV;
    if (lane == 31) { sb[256]=(b8>0.f)?__logf(b8)+lt:NEGV; }
    if (lane == 0)  { sb[257]=NEGV; sb[258]=NEGV; }
#undef BSTEP
}

__global__ void __launch_bounds__(128) ctc_kernel(
    const float* __restrict__ log_probs,
    const int*   __restrict__ targets,
    const int*   __restrict__ input_lengths,
    const int*   __restrict__ target_lengths,
    float*       __restrict__ out)
{
    // 4 warps x 3 halves = 48KB exactly; rings overlaid by log-alpha/beta
    // after each warp's final CPWAIT(0).
    __shared__ float ringall[4][3 * HALF];

    const int wid  = threadIdx.x >> 5;
    const int lane = threadIdx.x & 31;
    const int p    = wid >> 1;
    const bool bwd = wid & 1;
    const int n    = blockIdx.x * 2 + p;

    const float* lpn = log_probs + (size_t)n * C_CLASS;
    const int*   tg  = targets + n * S_TGT;
    const int inLen  = input_lengths[n];
    const int TL     = target_lengths[n];
    const int tm     = (inLen - 1) >> 1;          // fwd: 1..tm, bwd: inLen-1..tm+1

    float* ring = ringall[wid];
    const unsigned ring_s = (unsigned)__cvta_generic_to_shared(ring);
    const char* srcb = (const char*)lpn + lane * 16;

    if (!bwd) run_fwd(lpn, tg, tm, ring, ring_s, srcb, ring, lane);
    else      run_bwd(lpn, tg, tm, inLen, TL, ring, ring_s, srcb, ring, lane);
    __syncthreads();

    if (!bwd) {
        // ---- combine: P = sum_l alpha_tm(l) * (b(l)+b(l+1)+skip(l+2)*b(l+2)) ----
        const float* sa = ringall[2 * p];
        const float* sb = ringall[2 * p + 1];
        int4 tv = *(const int4*)(tg + 4 * lane);
        const int e0 = tv.x, e1 = tv.y, e2 = tv.z, e3 = tv.w;
        const float g1 = (e1 != e0) ? 1.f : 0.f;
        const float g2 = (e2 != e1) ? 1.f : 0.f;
        const float g3 = (e3 != e2) ? 1.f : 0.f;
        const float g4 = (lane < 31 && tg[4*lane+4] != e3) ? 1.f : 0.f;
        float E[8];
        const int l0 = 8 * lane;
        #pragma unroll
        for (int j = 0; j < 8; ++j) {
            float fl = (j==1)?g1 : (j==3)?g2 : (j==5)?g3 : (j==7)?g4 : 0.f;
            float x0 = sb[l0 + j];
            float x1 = sb[l0 + j + 1];
            float x2 = (fl > 0.f) ? sb[l0 + j + 2] : NEGV;
            float m3 = fmaxf(x0, fmaxf(x1, x2));
            float lse = m3 + __logf(__expf(x0-m3) + __expf(x1-m3) + __expf(x2-m3));
            E[j] = sa[l0 + j] + lse;
        }
        float E8 = (lane == 31) ? (sa[256] + sb[256]) : NEGV;
        float mx = E8;
        #pragma unroll
        for (int j = 0; j < 8; ++j) mx = fmaxf(mx, E[j]);
        #pragma unroll
        for (int o = 16; o > 0; o >>= 1)
            mx = fmaxf(mx, __shfl_xor_sync(FULLM, mx, o));
        float s = __expf(E8 - mx);
        #pragma unroll
        for (int j = 0; j < 8; ++j) s += __expf(E[j] - mx);
        #pragma unroll
        for (int o = 16; o > 0; o >>= 1)
            s += __shfl_xor_sync(FULLM, s, o);
        if (lane == 0) {
            float loss = -(mx + __logf(s));
            g_partial[n] = loss / (float)TL;
            __threadfence();
        }
        __syncwarp();
        unsigned tk = 0;
        if (lane == 0) tk = atomicAdd(&g_count, 1u);
        tk = __shfl_sync(FULLM, tk, 0);
        if (tk == NB - 1) {
            __threadfence();
            float acc = 0.f;
            #pragma unroll
            for (int i = 0; i < NB / 32; ++i)
                acc += __ldcg(&g_partial[lane + 32 * i]);
            #pragma unroll
            for (int o = 16; o > 0; o >>= 1)
                acc += __shfl_down_sync(FULLM, acc, o);
            if (lane == 0) {
                out[0] = acc * (1.f / (float)NB);
                g_count = 0;
            }
        }
    }
}

extern "C" void kernel_launch(void* const* d_in, const int* in_sizes, int n_in,
                              void* d_out, int out_size)
{
    const float* log_probs      = (const float*)d_in[0];
    const int*   targets        = (const int*)  d_in[1];
    const int*   input_lengths  = (const int*)  d_in[2];
    const int*   target_lengths = (const int*)  d_in[3];

    ctc_kernel<<<NB / 2, 128>>>(log_probs, targets, input_lengths,
                                target_lengths, (float*)d_out);
}